// round 5
// baseline (speedup 1.0000x reference)
#include <cuda_runtime.h>
#include <math.h>

#define Bv    8
#define Tv    4096
#define Dv    1024
#define Hv    8
#define Pv    1024
#define OUTv  1024
#define NWIN  128
#define WPB   4               // windows per block
#define WG    (NWIN/WPB)      // 32 window-groups
#define TSPAN 160             // tokens spanned per block (32*WPB + 32)
#define NCHUNK 5              // TSPAN / (8 warps * 4 tokens)

// ---------------- scratch (static device globals; no allocation) ----------------
__device__ __align__(16) float g_qk[Hv*Dv];             // 32 KB
__device__ __align__(16) float g_ypart[WG*Bv*Hv*Dv];    // 8 MB   [wg][b][h][d]
__device__ __align__(16) float g_y[Bv*Hv*Dv];           // 256 KB
__device__ __align__(16) float g_aggpart[32*Bv*Pv];     // 1 MB   [dseg][b][p]
__device__ __align__(16) float g_agg[Bv*Pv];            // 32 KB

// ---------------- helpers ----------------
__device__ __forceinline__ float wredsum(float v){
#pragma unroll
    for (int o = 16; o; o >>= 1) v += __shfl_xor_sync(0xffffffffu, v, o);
    return v;
}
__device__ __forceinline__ float wredmax(float v){
#pragma unroll
    for (int o = 16; o; o >>= 1) v = fmaxf(v, __shfl_xor_sync(0xffffffffu, v, o));
    return v;
}
__device__ __forceinline__ unsigned long long fma2(unsigned long long a,
                                                   unsigned long long b,
                                                   unsigned long long c){
    unsigned long long d;
    asm("fma.rn.f32x2 %0, %1, %2, %3;" : "=l"(d) : "l"(a), "l"(b), "l"(c));
    return d;
}
__device__ __forceinline__ unsigned long long add2(unsigned long long a,
                                                   unsigned long long b){
    unsigned long long d;
    asm("add.rn.f32x2 %0, %1, %2;" : "=l"(d) : "l"(a), "l"(b));
    return d;
}
__device__ __forceinline__ float2 unpack2(unsigned long long v){
    float2 r; asm("mov.b64 {%0, %1}, %2;" : "=f"(r.x), "=f"(r.y) : "l"(v)); return r;
}
__device__ __forceinline__ unsigned long long pack2(float lo, float hi){
    unsigned long long v; asm("mov.b64 %0, {%1, %2};" : "=l"(v) : "f"(lo), "f"(hi)); return v;
}
__device__ __forceinline__ unsigned long long shfl_xor64(unsigned long long v, int m){
    float2 p = unpack2(v);
    p.x = __shfl_xor_sync(0xffffffffu, p.x, m);
    p.y = __shfl_xor_sync(0xffffffffu, p.y, m);
    return pack2(p.x, p.y);
}

// ---------------- 1) qk[h,d] = sum_hd w_kv[d, h*128+hd] * query[h,hd] ----------------
__global__ void k_qk(const float* __restrict__ w_kv, const float* __restrict__ query){
    int g    = blockIdx.x * 8 + (threadIdx.x >> 5);
    int lane = threadIdx.x & 31;
    int h = g >> 10, d = g & 1023;
    float4 wv = *(const float4*)(w_kv + (size_t)d*2048 + h*128 + lane*4);
    float4 qv = *(const float4*)(query + h*128 + lane*4);
    float s = wv.x*qv.x + wv.y*qv.y + wv.z*qv.z + wv.w*qv.w;
    s = wredsum(s);
    if (lane == 0) g_qk[h*Dv + d] = s;
}

// ---------------- 2) fused logits + windowed softmax + weighted V-sum partials ----------------
// grid (wg=32, b=8), block 256 (8 warps). Block owns windows [4wg, 4wg+4),
// token span [128wg, 128wg+160). One DRAM pass over x; phase-C re-read is L2-hot.
__global__ void __launch_bounds__(256, 2) k_fused(const float* __restrict__ x){
    __shared__ float qs[Hv*Dv];                         // 32 KB
    __shared__ float lg[Hv][TSPAN+4];                   // 5.1 KB logits (pad vs conflicts)
    __shared__ unsigned long long cw2[Hv][TSPAN];       // 10 KB  (w,w) pairs

    int tid  = threadIdx.x;
    int wg   = blockIdx.x;
    int b    = blockIdx.y;
    int tbase = wg * (32*WPB);

#pragma unroll
    for (int i = 0; i < 8; i++)
        ((float4*)qs)[tid + i*256] = ((const float4*)g_qk)[tid + i*256];
    for (int i = tid; i < Hv*TSPAN; i += 256) ((unsigned long long*)cw2)[i] = 0ull;
    __syncthreads();

    int warp = tid >> 5, lane = tid & 31;
    const float scale = 0.08838834764831845f;           // 1/sqrt(128)

    // ---- phase A: logits, 20 tokens per warp, 5 chunks of 4 ----
#pragma unroll 1
    for (int c = 0; c < NCHUNK; c++){
        int tokl = warp*(4*NCHUNK) + c*4;
        unsigned long long r[32];                       // r[h*4+j]
#pragma unroll
        for (int v = 0; v < 32; v++) r[v] = 0ull;

        const float* rp[4];
#pragma unroll
        for (int j = 0; j < 4; j++){
            int t = tbase + tokl + j;
            t = t < Tv ? t : Tv - 1;                    // clamp OOB rows (masked later)
            rp[j] = x + ((size_t)b*Tv + t)*Dv + lane*4;
        }
#pragma unroll
        for (int i = 0; i < 8; i++){
            ulonglong2 xr[4];
#pragma unroll
            for (int j = 0; j < 4; j++)
                xr[j] = *(const ulonglong2*)(rp[j] + i*128);
#pragma unroll
            for (int h = 0; h < 8; h++){
                ulonglong2 q = *(const ulonglong2*)(qs + h*Dv + i*128 + lane*4);
#pragma unroll
                for (int j = 0; j < 4; j++){
                    r[h*4+j] = fma2(xr[j].x, q.x, r[h*4+j]);
                    r[h*4+j] = fma2(xr[j].y, q.y, r[h*4+j]);
                }
            }
        }
        // multi-value merge-butterfly: lane v ends holding full sum of r[v]
#pragma unroll
        for (int s = 16, n = 16; s >= 1; s >>= 1, n >>= 1){
            bool hi = (lane & s) != 0;
#pragma unroll
            for (int k = 0; k < 16; k++){
                if (k >= n) break;
                unsigned long long keep = hi ? r[k+n] : r[k];
                unsigned long long send = hi ? r[k]   : r[k+n];
                r[k] = add2(keep, shfl_xor64(send, s));
            }
        }
        float2 p = unpack2(r[0]);
        float sv = (p.x + p.y) * scale;
        int h = lane >> 2, j = lane & 3;
        int tok = tokl + j;
        lg[h][tok] = (tbase + tok < Tv) ? sv : -3.0e38f;
    }
    __syncthreads();

    // ---- phase B: WPB windows' softmax per head (warp == head), pair RMW ----
#pragma unroll
    for (int wi = 0; wi < WPB; wi++){
        int t0l = wi*32;
        float l0 = lg[warp][t0l + lane];
        float l1 = lg[warp][t0l + lane + 32];
        float m  = wredmax(fmaxf(l0, l1));
        float e0 = __expf(l0 - m);
        float e1 = __expf(l1 - m);
        float z  = wredsum(e0 + e1);
        float inv = (1.0f/128.0f) / z;
        float w0 = e0 * inv, w1 = e1 * inv;
        cw2[warp][t0l + lane]      = add2(cw2[warp][t0l + lane],      pack2(w0, w0));
        cw2[warp][t0l + lane + 32] = add2(cw2[warp][t0l + lane + 32], pack2(w1, w1));
    }
    __syncthreads();

    // ---- phase C: y partial, thread owns 4 d channels; x re-read hits L2 ----
    int tmax = TSPAN < (Tv - tbase) ? TSPAN : (Tv - tbase);
    const float* xb = x + ((size_t)b*Tv + tbase)*Dv + tid*4;
    unsigned long long acc[8][2];
#pragma unroll
    for (int h = 0; h < 8; h++){ acc[h][0] = 0ull; acc[h][1] = 0ull; }

#pragma unroll 4
    for (int tt = 0; tt < tmax; tt++){
        ulonglong2 xv = *(const ulonglong2*)(xb + (size_t)tt*Dv);
#pragma unroll
        for (int h = 0; h < 8; h++){
            unsigned long long w2 = cw2[h][tt];
            acc[h][0] = fma2(xv.x, w2, acc[h][0]);
            acc[h][1] = fma2(xv.y, w2, acc[h][1]);
        }
    }
    int dbase = tid*4;
#pragma unroll
    for (int h = 0; h < 8; h++){
        float2 a = unpack2(acc[h][0]);
        float2 c = unpack2(acc[h][1]);
        float4 o = make_float4(a.x, a.y, c.x, c.y);
        *(float4*)(g_ypart + ((((size_t)wg*Bv + b)*Hv + h)*Dv) + dbase) = o;
    }
}

// ---------------- 3) reduce y partials over window-groups ----------------
__global__ void k_yred(){
    int i = blockIdx.x*blockDim.x + threadIdx.x;        // 65536 = b*h*d
    float s = 0.f;
#pragma unroll
    for (int seg = 0; seg < WG; seg++) s += g_ypart[(size_t)seg*(Bv*Hv*Dv) + i];
    g_y[i] = s;
}

// ---------------- 4) agg partials: agg[b,p] = sum_d w_kv_v[d,p] * y[b, p/128, d] ----------------
// grid (dseg=32, pq=4), block 256: tid&63 -> 4 p's, tid>>6 -> batch pair
__global__ void k_agg(const float* __restrict__ w_kv){
    int tid  = threadIdx.x;
    int dseg = blockIdx.x;
    int p    = blockIdx.y*256 + (tid & 63)*4;
    int bg   = tid >> 6;                 // 0..3
    int b0   = bg*2, b1 = bg*2 + 1;
    int h    = p >> 7;
    float4 a0 = make_float4(0.f,0.f,0.f,0.f);
    float4 a1 = make_float4(0.f,0.f,0.f,0.f);
    const float* y0p = g_y + ((size_t)b0*Hv + h)*Dv;
    const float* y1p = g_y + ((size_t)b1*Hv + h)*Dv;
#pragma unroll 8
    for (int dd = 0; dd < 32; dd++){
        int d = dseg*32 + dd;
        float4 wv = *(const float4*)(w_kv + (size_t)d*2048 + 1024 + p);
        float y0 = y0p[d], y1 = y1p[d];
        a0.x += y0*wv.x; a0.y += y0*wv.y; a0.z += y0*wv.z; a0.w += y0*wv.w;
        a1.x += y1*wv.x; a1.y += y1*wv.y; a1.z += y1*wv.z; a1.w += y1*wv.w;
    }
    *(float4*)(g_aggpart + ((size_t)dseg*Bv + b0)*Pv + p) = a0;
    *(float4*)(g_aggpart + ((size_t)dseg*Bv + b1)*Pv + p) = a1;
}

// ---------------- 5) reduce agg partials ----------------
__global__ void k_aggred(){
    int i = blockIdx.x*blockDim.x + threadIdx.x;        // 8192
    float s = 0.f;
#pragma unroll
    for (int seg = 0; seg < 32; seg++) s += g_aggpart[(size_t)seg*(Bv*Pv) + i];
    g_agg[i] = s;
}

// ---------------- 6) out[b,o] = bias[o] + sum_p w_out[o,p]*agg[b,p] ----------------
__global__ void k_out(const float* __restrict__ w_out, const float* __restrict__ w_b,
                      float* __restrict__ out){
    __shared__ float aggs[Bv*Pv];                       // 32 KB
    int tid = threadIdx.x;
#pragma unroll
    for (int i = 0; i < 8; i++)
        ((float4*)aggs)[tid + i*256] = ((const float4*)g_agg)[tid + i*256];
    __syncthreads();

    int warp = tid >> 5, lane = tid & 31;
    int o = blockIdx.x*8 + warp;
    float acc[8];
#pragma unroll
    for (int b = 0; b < 8; b++) acc[b] = 0.f;
#pragma unroll
    for (int i = 0; i < 8; i++){
        float4 w4 = *(const float4*)(w_out + (size_t)o*Pv + i*128 + lane*4);
#pragma unroll
        for (int b = 0; b < 8; b++){
            float4 a4 = *(const float4*)(aggs + b*Pv + i*128 + lane*4);
            acc[b] += w4.x*a4.x + w4.y*a4.y + w4.z*a4.z + w4.w*a4.w;
        }
    }
#pragma unroll
    for (int b = 0; b < 8; b++) acc[b] = wredsum(acc[b]);
    if (lane == 0){
        float bias = w_b[o];
#pragma unroll
        for (int b = 0; b < 8; b++) out[(size_t)b*OUTv + o] = acc[b] + bias;
    }
}

// ---------------- launch ----------------
extern "C" void kernel_launch(void* const* d_in, const int* in_sizes, int n_in,
                              void* d_out, int out_size){
    const float* x     = (const float*)d_in[0];
    const float* w_kv  = (const float*)d_in[1];
    const float* query = (const float*)d_in[2];
    const float* w_out = (const float*)d_in[3];
    const float* w_b   = (const float*)d_in[4];
    float* out = (float*)d_out;

    k_qk    <<<1024, 256>>>(w_kv, query);
    dim3 gf(WG, Bv);
    k_fused <<<gf, 256>>>(x);
    k_yred  <<<256, 256>>>();
    dim3 ga(32, 4);
    k_agg   <<<ga, 256>>>(w_kv);
    k_aggred<<<32, 256>>>();
    k_out   <<<128, 256>>>(w_out, w_b, out);
}